// round 3
// baseline (speedup 1.0000x reference)
#include <cuda_runtime.h>

// EnhancedLIFNeuron on GB300: Conv1d(1,1,5,'same') + spatial attention + LIF scan.
// B=128, T=128, F=2048. Each thread owns TWO adjacent feature chains, processed
// with packed f32x2 arithmetic (FFMA2 path, only reachable via PTX).
// Stage x[b,:,f0:f0+128] tile in SMEM (64KB + 3 zero pad rows), closed-form
// mean for the spatial-attention scale, then conv+LIF with rolling window.

#define Tn 128
#define Fn 2048
#define Bn 128
#define BD 64          // threads per block; each owns 2 chains -> 128 chains/block
#define RS 128         // smem row stride in floats (chains per block)
#define SROWS (Tn + 3) // 3 zero-padded rows so the rolling window needs no predicate

typedef unsigned long long u64;

__device__ __forceinline__ u64 pk(float lo, float hi) {
    u64 r; asm("mov.b64 %0,{%1,%2};" : "=l"(r) : "f"(lo), "f"(hi)); return r;
}
__device__ __forceinline__ void upk(u64 v, float& lo, float& hi) {
    asm("mov.b64 {%0,%1},%2;" : "=f"(lo), "=f"(hi) : "l"(v));
}
__device__ __forceinline__ u64 f2fma(u64 a, u64 b, u64 c) {
    u64 d; asm("fma.rn.f32x2 %0,%1,%2,%3;" : "=l"(d) : "l"(a), "l"(b), "l"(c)); return d;
}
__device__ __forceinline__ u64 f2mul(u64 a, u64 b) {
    u64 d; asm("mul.rn.f32x2 %0,%1,%2;" : "=l"(d) : "l"(a), "l"(b)); return d;
}
__device__ __forceinline__ u64 f2add(u64 a, u64 b) {
    u64 d; asm("add.rn.f32x2 %0,%1,%2;" : "=l"(d) : "l"(a), "l"(b)); return d;
}
__device__ __forceinline__ float frcp(float a) {
    float r; asm("rcp.approx.ftz.f32 %0,%1;" : "=f"(r) : "f"(a)); return r;
}

#define SMASK 0x8000000080000000ull

__global__ __launch_bounds__(BD, 3)
void lif_kernel(const float* __restrict__ x,
                const float* __restrict__ thr0p,
                const float* __restrict__ convw,
                const float* __restrict__ convb,
                const float* __restrict__ sap,
                float* __restrict__ out)
{
    extern __shared__ float sm[];  // [SROWS][RS]
    const int tid = threadIdx.x;
    const int b   = blockIdx.x >> 4;
    const int f0  = (blockIdx.x & 15) << 7;

    // ---- stage tile (float4 coalesced) + zero pad rows ----
    const float4* __restrict__ src =
        reinterpret_cast<const float4*>(x + (size_t)b * Tn * Fn + f0);
    float4* s4 = reinterpret_cast<float4*>(sm);
    #pragma unroll 8
    for (int i = tid; i < Tn * (RS / 4); i += BD) {
        int t = i >> 5;          // RS/4 = 32 float4 per row
        int c = i & 31;
        s4[t * 32 + c] = src[(size_t)t * (Fn / 4) + c];
    }
    {
        float4 z4 = make_float4(0.f, 0.f, 0.f, 0.f);
        #pragma unroll
        for (int i = tid; i < 3 * 32; i += BD)
            s4[Tn * 32 + i] = z4;
    }
    __syncthreads();

    // ---- scalar constants ----
    const float thr0 = thr0p[0];
    const float w0 = convw[0], w1 = convw[1], w2 = convw[2], w3 = convw[3], w4 = convw[4];
    const float cb = convb[0];
    const float sa = sap[0];

    const u64* __restrict__ smp = reinterpret_cast<const u64*>(sm) + tid;  // packed pairs

    // ---- pass A: per-chain sum over t -> attention scale (closed form) ----
    u64 a0 = 0, a1 = 0, a2 = 0, a3 = 0;
    #pragma unroll 8
    for (int t = 0; t < Tn; t += 4) {
        a0 = f2add(a0, smp[(t + 0) * (RS / 2)]);
        a1 = f2add(a1, smp[(t + 1) * (RS / 2)]);
        a2 = f2add(a2, smp[(t + 2) * (RS / 2)]);
        a3 = f2add(a3, smp[(t + 3) * (RS / 2)]);
    }
    u64 S2 = f2add(f2add(a0, a1), f2add(a2, a3));
    u64 xb0   = smp[0];
    u64 xb1   = smp[1 * (RS / 2)];
    u64 xb126 = smp[126 * (RS / 2)];
    u64 xb127 = smp[127 * (RS / 2)];

    const float W = ((w0 + w1) + w2) + (w3 + w4);
    // sum_t conv_raw = W*S - (w3+w4)x0 - w4*x1 - w0*x126 - (w0+w1)*x127
    u64 acc = f2mul(pk(W, W), S2);
    acc = f2fma(pk(-(w3 + w4), -(w3 + w4)), xb0, acc);
    acc = f2fma(pk(-w4, -w4), xb1, acc);
    acc = f2fma(pk(-w0, -w0), xb126, acc);
    acc = f2fma(pk(-(w0 + w1), -(w0 + w1)), xb127, acc);
    u64 mean2 = f2fma(acc, pk(1.f / Tn, 1.f / Tn), pk(cb, cb));

    float mlo, mhi; upk(mean2, mlo, mhi);
    float wlo = 1.0f / (1.0f + __expf(-sa * mlo));
    float whi = 1.0f / (1.0f + __expf(-sa * mhi));
    const u64 scale2 = pk(1.0f + 0.5f * wlo, 1.0f + 0.5f * whi);   // GAMMA=0.5

    // ---- packed constants ----
    const float PI = 3.14159265358979323846f;
    const u64 W0 = pk(w0, w0), W1 = pk(w1, w1), W2 = pk(w2, w2),
              W3 = pk(w3, w3), W4 = pk(w4, w4), CB = pk(cb, cb);
    const u64 DEC  = pk(0.9f, 0.9f);
    const u64 CARG = pk(PI * 0.5f, PI * 0.5f);
    const u64 CSPK = pk(0.5f / PI, 0.5f / PI);
    const u64 QRT  = pk(0.25f, 0.25f);
    const u64 ALP  = pk(0.9f, 0.9f);
    const u64 CAVG = pk(0.1f / 3.0f, 0.1f / 3.0f);
    const u64 CT0  = pk(0.1f * thr0, 0.1f * thr0);
    const float PIO2 = 1.57079632679489662f;
    // atan(x) ~ x * P(x^2), |x|<=1, degree-11 odd minimax
    const u64 A0 = pk( 0.99997726f,  0.99997726f);
    const u64 A1 = pk(-0.33262347f, -0.33262347f);
    const u64 A2 = pk( 0.19354346f,  0.19354346f);
    const u64 A3 = pk(-0.11643287f, -0.11643287f);
    const u64 A4 = pk( 0.05265332f,  0.05265332f);
    const u64 A5 = pk(-0.01172120f, -0.01172120f);

    // ---- LIF state (packed) ----
    u64 mem = 0, thr = pk(thr0, thr0), h1 = 0, h2 = 0;
    u64 xm2 = 0, xm1 = 0;
    u64 xc  = smp[0];
    u64 xp1 = smp[1 * (RS / 2)];
    u64 xp2 = smp[2 * (RS / 2)];

    u64* __restrict__ op =
        reinterpret_cast<u64*>(out + (size_t)b * Tn * Fn + f0) + tid;

    #pragma unroll 4
    for (int t = 0; t < Tn; t++) {
        // conv (cross-correlation, 'SAME') + bias
        u64 conv = f2fma(W0, xm2,
                   f2fma(W1, xm1,
                   f2fma(W2, xc,
                   f2fma(W3, xp1,
                   f2fma(W4, xp2, CB)))));
        mem = f2fma(DEC, mem, f2mul(conv, scale2));

        // arg = (mem - thr) * pi/2
        u64 arg = f2fma(f2add(mem, thr ^ SMASK), CARG, 0ull);
        arg = f2mul(f2add(mem, thr ^ SMASK), CARG);

        // ---- packed atan ----
        u64 zz = f2mul(arg, arg);
        u64 z4 = f2mul(zz, zz);
        u64 qs = f2fma(f2fma(f2fma(A5, zz, A4), z4, f2fma(A3, zz, A2)), z4,
                       f2fma(A1, zz, A0));
        u64 small_r = f2mul(arg, qs);

        float zlo, zhi; upk(arg, zlo, zhi);
        u64 rt = pk(frcp(zlo), frcp(zhi));
        u64 rr = f2mul(rt, rt);
        u64 r4 = f2mul(rr, rr);
        u64 ps = f2fma(f2fma(f2fma(A5, rr, A4), r4, f2fma(A3, rr, A2)), r4,
                       f2fma(A1, rr, A0));
        u64 sg = pk(copysignf(PIO2, zlo), copysignf(PIO2, zhi));
        u64 big_r = f2fma(rt ^ SMASK, ps, sg);

        float slo, shi, blo, bhi;
        upk(small_r, slo, shi); upk(big_r, blo, bhi);
        float alo = (fabsf(zlo) > 1.0f) ? blo : slo;
        float ahi = (fabsf(zhi) > 1.0f) ? bhi : shi;
        u64 at2 = pk(alo, ahi);
        // -------------------

        u64 spike = f2fma(at2, CSPK, QRT);
        u64 s3 = f2add(f2add(h1, h2), spike);
        thr = f2fma(ALP, thr, f2fma(CAVG, s3, CT0));
        mem = f2fma(spike ^ SMASK, thr, mem);

        op[(size_t)t * (Fn / 2)] = spike;

        h1 = h2; h2 = spike;
        xm2 = xm1; xm1 = xc; xc = xp1; xp1 = xp2;
        xp2 = smp[(t + 3) * (RS / 2)];   // padded rows -> no predicate
    }

    // final membrane potential
    u64* mo = reinterpret_cast<u64*>(out + (size_t)Bn * Tn * Fn + (size_t)b * Fn + f0) + tid;
    *mo = mem;
}

extern "C" void kernel_launch(void* const* d_in, const int* in_sizes, int n_in,
                              void* d_out, int out_size)
{
    (void)in_sizes; (void)n_in; (void)out_size;
    const float* x    = (const float*)d_in[0];
    const float* thr0 = (const float*)d_in[1];
    const float* cw   = (const float*)d_in[2];
    const float* cbp  = (const float*)d_in[3];
    const float* sa   = (const float*)d_in[4];
    float* out = (float*)d_out;

    const int smem = SROWS * RS * (int)sizeof(float);
    cudaFuncSetAttribute(lif_kernel, cudaFuncAttributeMaxDynamicSharedMemorySize, smem);
    lif_kernel<<<Bn * (Fn / RS), BD, smem>>>(x, thr0, cw, cbp, sa, out);
}

// round 4
// speedup vs baseline: 1.0911x; 1.0911x over previous
#include <cuda_runtime.h>

// EnhancedLIFNeuron on GB300: Conv1d(1,1,5,'same') + spatial attention + LIF scan.
// B=128, T=128, F=2048. One thread = one (b,f) chain. 128 threads/block,
// 3 blocks/SM (64KB smem tile each) = 12 warps/SM.
// Fast branch-free atan: half-angle transform + deg-9 odd minimax poly,
// with the x2 and 1/(2pi) factors folded into the coefficients.

#define Tn 128
#define Fn 2048
#define Bn 128
#define CH 128         // chains per block == blockDim.x
#define SROWS (Tn + 3) // 3 zero pad rows -> rolling window needs no predicate

__device__ __forceinline__ float fsqrt_ap(float a) {
    float r; asm("sqrt.approx.ftz.f32 %0,%1;" : "=f"(r) : "f"(a)); return r;
}
__device__ __forceinline__ float frcp_ap(float a) {
    float r; asm("rcp.approx.ftz.f32 %0,%1;" : "=f"(r) : "f"(a)); return r;
}

__global__ __launch_bounds__(CH, 3)
void lif_kernel(const float* __restrict__ x,
                const float* __restrict__ thr0p,
                const float* __restrict__ convw,
                const float* __restrict__ convb,
                const float* __restrict__ sap,
                float* __restrict__ out)
{
    extern __shared__ float sm[];  // [SROWS][CH]
    const int tid = threadIdx.x;
    const int b   = blockIdx.x >> 4;          // Fn/CH = 16 blocks per batch
    const int f0  = (blockIdx.x & 15) << 7;   // * CH

    // ---- stage tile: x[b, :, f0:f0+128] (float4 coalesced) + zero pad ----
    const float4* __restrict__ src =
        reinterpret_cast<const float4*>(x + (size_t)b * Tn * Fn + f0);
    float4* s4 = reinterpret_cast<float4*>(sm);
    #pragma unroll 8
    for (int i = tid; i < Tn * (CH / 4); i += CH) {
        int t = i >> 5;        // CH/4 = 32 float4 per row
        int c = i & 31;
        s4[t * 32 + c] = src[(size_t)t * (Fn / 4) + c];
    }
    if (tid < 96) s4[Tn * 32 + tid] = make_float4(0.f, 0.f, 0.f, 0.f);
    __syncthreads();

    // ---- scalars ----
    const float thr0 = thr0p[0];
    const float w0 = convw[0], w1 = convw[1], w2 = convw[2], w3 = convw[3], w4 = convw[4];
    const float cb = convb[0];
    const float sa = sap[0];

    // ---- pass A: per-chain sum over t -> attention scale (closed form) ----
    float a0 = 0.f, a1 = 0.f, a2 = 0.f, a3 = 0.f;
    #pragma unroll 8
    for (int t = 0; t < Tn; t += 4) {
        a0 += sm[(t + 0) * CH + tid];
        a1 += sm[(t + 1) * CH + tid];
        a2 += sm[(t + 2) * CH + tid];
        a3 += sm[(t + 3) * CH + tid];
    }
    const float S = (a0 + a1) + (a2 + a3);
    const float xb0   = sm[0 * CH + tid];
    const float xb1   = sm[1 * CH + tid];
    const float xb126 = sm[126 * CH + tid];
    const float xb127 = sm[127 * CH + tid];
    const float W = ((w0 + w1) + w2) + (w3 + w4);
    // sum_t conv_raw = W*S - (w3+w4)x0 - w4*x1 - w0*x126 - (w0+w1)*x127
    float mean = (W * S - (w3 + w4) * xb0 - w4 * xb1
                        - w0 * xb126 - (w0 + w1) * xb127) * (1.0f / Tn) + cb;
    const float attw  = 1.0f / (1.0f + __expf(-sa * mean));
    const float scale = 1.0f + 0.5f * attw;           // GAMMA = 0.5

    // ---- constants ----
    const float PI    = 3.14159265358979323846f;
    const float CARG  = PI * 0.5f;
    const float CTHR0 = 0.1f * thr0;                  // (1-ALPHA)*thr0
    const float CAVG  = 0.1f / 3.0f;                  // BETA/3
    // atan(z) = 2*atan(t), t = z/(1+sqrt(1+z^2)); spike = atan(z)/(2pi)+0.25
    //  => spike = t*P(t^2) + 0.25 with P = (2/(2pi)) * minimax deg-9 poly
    const float INVPI = 1.0f / PI;
    const float P0 =  0.9998660f  * INVPI;
    const float P1 = -0.3302995f  * INVPI;
    const float P2 =  0.1801410f  * INVPI;
    const float P3 = -0.0851330f  * INVPI;
    const float P4 =  0.0208351f  * INVPI;

    // fold scale into conv weights (conv output only used scaled)
    const float v0 = w0 * scale, v1 = w1 * scale, v2 = w2 * scale,
                v3 = w3 * scale, v4 = w4 * scale, vb = cb * scale;

    // ---- LIF state ----
    float mem = 0.f, thr = thr0, h2 = 0.f, h12 = 0.f;  // h12 = h1 + h2
    float xm2 = 0.f, xm1 = 0.f;
    float xc  = sm[0 * CH + tid];
    float xp1 = sm[1 * CH + tid];
    float xp2 = sm[2 * CH + tid];

    float* __restrict__ op = out + (size_t)b * Tn * Fn + f0 + tid;

    #pragma unroll 4
    for (int t = 0; t < Tn; t++) {
        // scaled conv (cross-correlation, 'SAME') + scaled bias
        float xs = fmaf(v0, xm2,
                   fmaf(v1, xm1,
                   fmaf(v2, xc,
                   fmaf(v3, xp1,
                   fmaf(v4, xp2, vb)))));
        mem = fmaf(0.9f, mem, xs);                    // DECAY

        // spike = atan(pi*(mem-thr)/2)/(2pi) + 0.25, branch-free
        float z  = (mem - thr) * CARG;
        float zz = z * z;
        float s  = fsqrt_ap(1.0f + zz);
        float rt = frcp_ap(1.0f + s);
        float tq = z * rt;
        float tt = tq * tq;
        float p  = fmaf(fmaf(fmaf(fmaf(P4, tt, P3), tt, P2), tt, P1), tt, P0);
        float spike = fmaf(tq, p, 0.25f);

        float s3 = h12 + spike;                       // h1 + h2 + spike
        thr = fmaf(0.9f, thr, fmaf(CAVG, s3, CTHR0)); // ALPHA, BETA
        mem = fmaf(-spike, thr, mem);

        op[(size_t)t * Fn] = spike;

        h12 = h2 + spike; h2 = spike;                 // shift history
        xm2 = xm1; xm1 = xc; xc = xp1; xp1 = xp2;
        xp2 = sm[(t + 3) * CH + tid];                 // padded rows: no predicate
    }

    // final membrane potential
    out[(size_t)Bn * Tn * Fn + (size_t)b * Fn + f0 + tid] = mem;
}

extern "C" void kernel_launch(void* const* d_in, const int* in_sizes, int n_in,
                              void* d_out, int out_size)
{
    (void)in_sizes; (void)n_in; (void)out_size;
    const float* x    = (const float*)d_in[0];
    const float* thr0 = (const float*)d_in[1];
    const float* cw   = (const float*)d_in[2];
    const float* cbp  = (const float*)d_in[3];
    const float* sa   = (const float*)d_in[4];
    float* out = (float*)d_out;

    const int smem = SROWS * CH * (int)sizeof(float);
    cudaFuncSetAttribute(lif_kernel, cudaFuncAttributeMaxDynamicSharedMemorySize, smem);
    lif_kernel<<<Bn * (Fn / CH), CH, smem>>>(x, thr0, cw, cbp, sa, out);
}